// round 8
// baseline (speedup 1.0000x reference)
#include <cuda_runtime.h>
#include <cuda_bf16.h>
#include <math.h>
#include <stdint.h>

#define B_   4096
#define D_   5000
#define H_   512
#define H2_  1024
#define Z_   64
#define KP_D 5056
#define NP_D 5120

typedef __nv_bfloat16 bf16;

// ---------------- scratch (static device globals; zero-initialized) ---------
__device__ float g_h  [B_ * H_ ];
__device__ float g_w  [B_ * D_ ];
__device__ float g_h1b[B_ * H_ ];
__device__ float g_ml [B_ * 128];
__device__ float g_z  [B_ * Z_ ];
__device__ float g_d  [B_ * H2_];
__device__ float g_mlw[H_ * 128];
__device__ float g_mlb[128];
__device__ float g_scale[H_];
__device__ float g_shift[H_];
__device__ __align__(16) bf16 sx_h [B_ * KP_D], sx_l [B_ * KP_D];
__device__ __align__(16) bf16 shh  [B_ * H_  ], shl  [B_ * H_  ];
__device__ __align__(16) bf16 sxm_h[B_ * KP_D], sxm_l[B_ * KP_D];
__device__ __align__(16) bf16 sa1_h[B_ * H2_ ], sa1_l[B_ * H2_ ];
__device__ __align__(16) bf16 sa2_h[B_ * H_  ], sa2_l[B_ * H_  ];
__device__ __align__(16) bf16 sa3_h[B_ * H_  ], sa3_l[B_ * H_  ];
__device__ __align__(16) bf16 sd_h [B_ * H2_ ], sd_l [B_ * H2_ ];
__device__ __align__(16) bf16 w1T_h[H_   * KP_D], w1T_l[H_   * KP_D];
__device__ __align__(16) bf16 w2T_h[NP_D * H_  ], w2T_l[NP_D * H_  ];
__device__ __align__(16) bf16 e1T_h[H2_  * KP_D], e1T_l[H2_  * KP_D];
__device__ __align__(16) bf16 e2T_h[H_   * H2_ ], e2T_l[H_   * H2_ ];
__device__ __align__(16) bf16 e3T_h[H_   * H_  ], e3T_l[H_   * H_  ];
__device__ __align__(16) bf16 e4T_h[H_   * H_  ], e4T_l[H_   * H_  ];
__device__ __align__(16) bf16 d2T_h[NP_D * H2_ ], d2T_l[NP_D * H2_ ];

// ---------------- PTX helpers (base ISA only) -------------------------------
__device__ __forceinline__ uint32_t smem_u32(const void* p) {
    uint32_t a;
    asm("{ .reg .u64 t; cvta.to.shared.u64 t, %1; cvt.u32.u64 %0, t; }" : "=r"(a) : "l"(p));
    return a;
}
__device__ __forceinline__ void cp16(uint32_t s, const void* g) {
    asm volatile("cp.async.cg.shared.global [%0], [%1], 16;" :: "r"(s), "l"(g));
}
#define CP_COMMIT() asm volatile("cp.async.commit_group;" ::: "memory")
template<int N> __device__ __forceinline__ void cp_wait() {
    asm volatile("cp.async.wait_group %0;" :: "n"(N) : "memory");
}
__device__ __forceinline__ void ldsm4(uint32_t* r, uint32_t addr) {
    asm volatile("ldmatrix.sync.aligned.m8n8.x4.shared.b16 {%0,%1,%2,%3}, [%4];"
        : "=r"(r[0]), "=r"(r[1]), "=r"(r[2]), "=r"(r[3]) : "r"(addr));
}
__device__ __forceinline__ void mma16816(float* c, const uint32_t* a, const uint32_t* b) {
    asm volatile("mma.sync.aligned.m16n8k16.row.col.f32.bf16.bf16.f32 "
        "{%0,%1,%2,%3}, {%4,%5,%6,%7}, {%8,%9}, {%0,%1,%2,%3};"
        : "+f"(c[0]), "+f"(c[1]), "+f"(c[2]), "+f"(c[3])
        : "r"(a[0]), "r"(a[1]), "r"(a[2]), "r"(a[3]), "r"(b[0]), "r"(b[1]));
}

// ---------------- HMMA split-bf16 GEMM --------------------------------------
// C[4096,N] = epi(A @ Bt^T + bias). A=[M][Kpad] hi/lo, Bt=[Nrows][Kpad] hi/lo,
// K-major bf16, Kpad % 64 == 0. CTA tile 128 x BN, K-chunk 64, NSTG-stage
// cp.async pipeline, 3-pass split accumulate (AhBh + AhBl + AlBh) in fp32.
template<int BN>
__device__ __forceinline__ void fill_chunk(uint32_t sb,
    const bf16* Ah, const bf16* Al, const bf16* Bh, const bf16* Bl,
    int ld, int bm, int bn, int k0, int tid)
{
    int rl = tid >> 3, c8 = tid & 7;
#pragma unroll
    for (int i = 0; i < 4; i++) {                       // A: 128 rows
        int row = rl + 32 * i;
        uint32_t bo = row * 128 + c8 * 16;
        uint32_t sw = bo ^ ((bo >> 3) & 0x70);
        size_t ga = ((size_t)(bm + row) * ld + k0) * 2 + c8 * 16;
        cp16(sb + sw,         (const char*)Ah + ga);
        cp16(sb + 16384 + sw, (const char*)Al + ga);
    }
#pragma unroll
    for (int i = 0; i < BN / 32; i++) {                 // B: BN rows
        int row = rl + 32 * i;
        uint32_t bo = row * 128 + c8 * 16;
        uint32_t sw = bo ^ ((bo >> 3) & 0x70);
        size_t gb = ((size_t)(bn + row) * ld + k0) * 2 + c8 * 16;
        cp16(sb + 32768 + sw,            (const char*)Bh + gb);
        cp16(sb + 32768 + BN * 128 + sw, (const char*)Bl + gb);
    }
}

// EPI: 0 bias, 1 leaky, 2 sigmoid, 3 gumbel
template<int EPI, bool OF32, bool OSPL, int BN, int NSTG>
__global__ void __launch_bounds__(256, 1) tgemm_k(
    const bf16* __restrict__ Ah, const bf16* __restrict__ Al,
    const bf16* __restrict__ Bh, const bf16* __restrict__ Bl, int ldab,
    const float* __restrict__ bias, const float* __restrict__ U,
    float* __restrict__ Cf, bf16* __restrict__ Chi, bf16* __restrict__ Clo,
    int ldspl, int N, int Kpad)
{
    constexpr int WNT = BN / 4;        // warp N-tile: 32 or 64
    constexpr int NJB = WNT / 16;      // B ldsm groups: 2 or 4
    constexpr int STG = 32768 + BN * 256;

    extern __shared__ char dsm[];
    uint32_t sbase = (smem_u32(dsm) + 1023u) & ~1023u;

    const int tid  = threadIdx.x;
    const int wid  = tid >> 5, lane = tid & 31;
    const int wm   = wid & 1,  wn   = wid >> 1;
    const int bm   = blockIdx.y * 128;
    const int bn   = blockIdx.x * BN;
    const int NC   = Kpad >> 6;

    float acc[4][2 * NJB][4];
#pragma unroll
    for (int mi = 0; mi < 4; mi++)
#pragma unroll
        for (int nj = 0; nj < 2 * NJB; nj++)
#pragma unroll
            for (int q = 0; q < 4; q++) acc[mi][nj][q] = 0.f;

#pragma unroll
    for (int s = 0; s < NSTG - 1; s++) {
        if (s < NC) fill_chunk<BN>(sbase + s * STG, Ah, Al, Bh, Bl, ldab, bm, bn, s << 6, tid);
        CP_COMMIT();
    }

    for (int c = 0; c < NC; ++c) {
        cp_wait<NSTG - 2>();
        __syncthreads();
        int pf = c + NSTG - 1;
        if (pf < NC)
            fill_chunk<BN>(sbase + (pf % NSTG) * STG, Ah, Al, Bh, Bl, ldab, bm, bn, pf << 6, tid);
        CP_COMMIT();

        uint32_t sA  = sbase + (c % NSTG) * STG;
        uint32_t sAl = sA + 16384, sB = sA + 32768, sBl = sB + BN * 128;

#pragma unroll
        for (int ks = 0; ks < 4; ks++) {
            uint32_t ah[4][4], al[4][4];
            {
                int arow = wm * 64 + (lane & 15);
                uint32_t akb = ks * 32 + ((lane >> 4) << 4);
#pragma unroll
                for (int mi = 0; mi < 4; mi++) {
                    uint32_t off = (uint32_t)(arow + mi * 16) * 128 + akb;
                    uint32_t sw = off ^ ((off >> 3) & 0x70);
                    ldsm4(ah[mi], sA + sw);
                    ldsm4(al[mi], sAl + sw);
                }
            }
            int brow = wn * WNT + ((lane >> 4) << 3) + (lane & 7);
            uint32_t bkb = ks * 32 + (((lane >> 3) & 1) << 4);
#pragma unroll
            for (int jb = 0; jb < NJB; jb++) {
                uint32_t bh4[4], bl4[4];
                uint32_t off = (uint32_t)(brow + jb * 16) * 128 + bkb;
                uint32_t sw = off ^ ((off >> 3) & 0x70);
                ldsm4(bh4, sB + sw);
                ldsm4(bl4, sBl + sw);
#pragma unroll
                for (int half = 0; half < 2; half++) {
                    int nj = jb * 2 + half;
                    const uint32_t* Bh2 = &bh4[half * 2];
                    const uint32_t* Bl2 = &bl4[half * 2];
#pragma unroll
                    for (int mi = 0; mi < 4; mi++) {
                        mma16816(acc[mi][nj], ah[mi], Bh2);
                        mma16816(acc[mi][nj], ah[mi], Bl2);
                        mma16816(acc[mi][nj], al[mi], Bh2);
                    }
                }
            }
        }
    }

    // epilogue straight from registers
#pragma unroll
    for (int mi = 0; mi < 4; mi++) {
#pragma unroll
        for (int nj = 0; nj < 2 * NJB; nj++) {
            int row0 = bm + wm * 64 + mi * 16 + (lane >> 2);
            int col0 = bn + wn * WNT + nj * 8 + (lane & 3) * 2;
#pragma unroll
            for (int h = 0; h < 2; h++) {
                int m = row0 + h * 8;
#pragma unroll
                for (int i = 0; i < 2; i++) {
                    int n = col0 + i;
                    if (n < N) {
                        float v = acc[mi][nj][h * 2 + i] + __ldg(&bias[n]);
                        if (EPI == 1) v = (v > 0.f) ? v : 0.01f * v;
                        else if (EPI == 2) v = 1.0f / (1.0f + __expf(-v));
                        else if (EPI == 3) {
                            float u = U[(size_t)m * N + n];
                            u = (1.0f - 1e-30f) * u + 1e-30f;
                            v += __logf(-__logf(u));
                        }
                        if (OF32) Cf[(size_t)m * N + n] = v;
                        if (OSPL) {
                            bf16 hh = __float2bfloat16(v);
                            Chi[(size_t)m * ldspl + n] = hh;
                            Clo[(size_t)m * ldspl + n] = __float2bfloat16(v - __bfloat162float(hh));
                        }
                    }
                }
            }
        }
    }
}

// ---------------- SIMT fp32 GEMM (small layers) ----------------
template<int EPI>
__global__ void __launch_bounds__(256) sgemm_k(
    const float* __restrict__ A, const float* __restrict__ Bm,
    const float* __restrict__ bias, float* __restrict__ C, int M, int N, int K)
{
    constexpr int BM = 128, BNt = 128, BK = 8, TM = 8, TN = 8;
    __shared__ float As[BK][BM];
    __shared__ float Bs[BK][BNt];
    const int tid = threadIdx.x;
    const int tx = tid & 15, ty = tid >> 4;
    const int bm = blockIdx.y * BM, bn = blockIdx.x * BNt;
    const int aIdx = tid * 4, am = aIdx >> 3, ak = aIdx & 7;
    const int bIdx = tid * 4, bk = bIdx >> 7, bn4 = bIdx & 127;
    float acc[TM][TN];
#pragma unroll
    for (int i = 0; i < TM; i++)
#pragma unroll
        for (int j = 0; j < TN; j++) acc[i][j] = 0.f;
    const float* Aptr = A + (size_t)(bm + am) * K;
    for (int k0 = 0; k0 < K; k0 += BK) {
        float4 av = *(const float4*)(Aptr + k0 + ak);
        As[ak + 0][am] = av.x; As[ak + 1][am] = av.y;
        As[ak + 2][am] = av.z; As[ak + 3][am] = av.w;
        const float* Bp = Bm + (size_t)(k0 + bk) * N + bn + bn4;
        int nr = N - (bn + bn4);
        Bs[bk][bn4 + 0] = (0 < nr) ? Bp[0] : 0.f;
        Bs[bk][bn4 + 1] = (1 < nr) ? Bp[1] : 0.f;
        Bs[bk][bn4 + 2] = (2 < nr) ? Bp[2] : 0.f;
        Bs[bk][bn4 + 3] = (3 < nr) ? Bp[3] : 0.f;
        __syncthreads();
#pragma unroll
        for (int kk = 0; kk < BK; kk++) {
            float ar[TM], br[TN];
#pragma unroll
            for (int i = 0; i < TM; i++) ar[i] = As[kk][ty * TM + i];
#pragma unroll
            for (int j = 0; j < TN; j++) br[j] = Bs[kk][tx * TN + j];
#pragma unroll
            for (int i = 0; i < TM; i++)
#pragma unroll
                for (int j = 0; j < TN; j++)
                    acc[i][j] = fmaf(ar[i], br[j], acc[i][j]);
        }
        __syncthreads();
    }
#pragma unroll
    for (int i = 0; i < TM; i++)
#pragma unroll
        for (int j = 0; j < TN; j++) {
            int n = bn + tx * TN + j;
            if (n < N) {
                float v = acc[i][j] + bias[n];
                if (EPI == 1) v = (v > 0.f) ? v : 0.01f * v;
                C[(size_t)(bm + ty * TM + i) * N + n] = v;
            }
        }
}

// ---------------- BN stats (coalesced: 32 cols x 8 row-threads) -------------
__global__ void bnstats_k(const float* __restrict__ Hm, const float* __restrict__ gamma,
                          const float* __restrict__ beta, float* __restrict__ sc,
                          float* __restrict__ sh)
{
    int col = blockIdx.x * 32 + threadIdx.x;
    int ty  = threadIdx.y;
    float s = 0.f, q = 0.f;
    for (int r = ty; r < B_; r += 8) {
        float v = Hm[(size_t)r * H_ + col];
        s += v; q += v * v;
    }
    __shared__ float S[8][32], Q[8][32];
    S[ty][threadIdx.x] = s; Q[ty][threadIdx.x] = q;
    __syncthreads();
    if (ty == 0) {
        float SS = 0.f, QQ = 0.f;
#pragma unroll
        for (int i = 0; i < 8; i++) { SS += S[i][threadIdx.x]; QQ += Q[i][threadIdx.x]; }
        float mean = SS / (float)B_;
        float var  = QQ / (float)B_ - mean * mean;
        float scale = gamma[col] * rsqrtf(var + 1e-5f);
        sc[col] = scale; sh[col] = beta[col] - mean * scale;
    }
}

// ---------------- continuous top-k (+ fused split xm) ----------------
__global__ void __launch_bounds__(512) topk_k(const float* __restrict__ W,
                                              const float* __restrict__ X,
                                              bf16* __restrict__ XMh, bf16* __restrict__ XMl)
{
    constexpr int NT = 512, EPT = 10;
    int row = blockIdx.x;
    const float* wr = W + (size_t)row * D_;
    int t = threadIdx.x;
    float wv[EPT], sv[EPT];
#pragma unroll
    for (int i = 0; i < EPT; i++) {
        int idx = t + i * NT;
        wv[i] = (idx < D_) ? wr[idx] : -3.0e38f;
        sv[i] = 0.f;
    }
    __shared__ float red[16];
    __shared__ float bc_max, bc_sum;
    int w = t >> 5, l = t & 31;
    for (int it = 0; it < 50; it++) {
        float m = wv[0];
#pragma unroll
        for (int i = 1; i < EPT; i++) m = fmaxf(m, wv[i]);
#pragma unroll
        for (int o = 16; o > 0; o >>= 1) m = fmaxf(m, __shfl_xor_sync(0xffffffffu, m, o));
        if (l == 0) red[w] = m;
        __syncthreads();
        if (t == 0) {
            float mm = red[0];
            for (int i = 1; i < 16; i++) mm = fmaxf(mm, red[i]);
            bc_max = mm;
        }
        __syncthreads();
        float mx = bc_max, s = 0.f, ev[EPT];
#pragma unroll
        for (int i = 0; i < EPT; i++) {
            float a = (wv[i] - mx) * 10.0f;
            float e = (a > -20.f) ? __expf(a) : 0.f;
            ev[i] = e; s += e;
        }
#pragma unroll
        for (int o = 16; o > 0; o >>= 1) s += __shfl_xor_sync(0xffffffffu, s, o);
        if (l == 0) red[w] = s;
        __syncthreads();
        if (t == 0) {
            float ss = 0.f;
            for (int i = 0; i < 16; i++) ss += red[i];
            bc_sum = ss;
        }
        __syncthreads();
        float inv = 1.0f / bc_sum;
#pragma unroll
        for (int i = 0; i < EPT; i++) {
            float oh = ev[i] * inv;
            sv[i] += oh;
            if (oh > 0.f) wv[i] += __logf(fmaxf(1.0f - oh, 1e-30f));
        }
    }
    const float* xr = X + (size_t)row * D_;
    size_t ob = (size_t)row * KP_D;
#pragma unroll
    for (int i = 0; i < EPT; i++) {
        int idx = t + i * NT;
        if (idx < D_) {
            float v = xr[idx] * sv[i];
            bf16 h = __float2bfloat16(v);
            XMh[ob + idx] = h;
            XMl[ob + idx] = __float2bfloat16(v - __bfloat162float(h));
        }
    }
}

// ---------------- conversion / prep ----------------
__global__ void xsplit_k(const float* __restrict__ x, bf16* __restrict__ hi, bf16* __restrict__ lo)
{
    int m = blockIdx.x;
    for (int c = threadIdx.x; c < D_; c += blockDim.x) {
        float v = x[(size_t)m * D_ + c];
        bf16 h = __float2bfloat16(v);
        size_t o = (size_t)m * KP_D + c;
        hi[o] = h; lo[o] = __float2bfloat16(v - __bfloat162float(h));
    }
}
__global__ void hsplit_k(const float* __restrict__ Hm, const float* __restrict__ sc,
                         const float* __restrict__ sh, bf16* __restrict__ hi, bf16* __restrict__ lo)
{
    int m = blockIdx.x, c = threadIdx.x;
    float v = fmaxf(fmaf(Hm[(size_t)m * H_ + c], sc[c], sh[c]), 0.f);
    bf16 h = __float2bfloat16(v);
    size_t o = (size_t)m * H_ + c;
    hi[o] = h; lo[o] = __float2bfloat16(v - __bfloat162float(h));
}
__global__ void dsplit_k(const float* __restrict__ Dm, bf16* __restrict__ hi, bf16* __restrict__ lo)
{
    int m = blockIdx.x;
    for (int c = threadIdx.x; c < H2_; c += blockDim.x) {
        float v = Dm[(size_t)m * H2_ + c];
        bf16 h = __float2bfloat16(v);
        size_t o = (size_t)m * H2_ + c;
        hi[o] = h; lo[o] = __float2bfloat16(v - __bfloat162float(h));
    }
}
__global__ void wsplitT_k(const float* __restrict__ W, int K, int N, int Kpad,
                          bf16* __restrict__ Thi, bf16* __restrict__ Tlo)
{
    __shared__ float t[32][33];
    int kb = blockIdx.x * 32, nb = blockIdx.y * 32;
    int tx = threadIdx.x, ty = threadIdx.y;
#pragma unroll
    for (int j = 0; j < 4; j++) {
        int k = kb + ty + j * 8, n = nb + tx;
        t[ty + j * 8][tx] = (k < K && n < N) ? W[(size_t)k * N + n] : 0.f;
    }
    __syncthreads();
#pragma unroll
    for (int j = 0; j < 4; j++) {
        int n = nb + ty + j * 8, k = kb + tx;
        if (n < N && k < K) {
            float v = t[tx][ty + j * 8];
            bf16 h = __float2bfloat16(v);
            Thi[(size_t)n * Kpad + k] = h;
            Tlo[(size_t)n * Kpad + k] = __float2bfloat16(v - __bfloat162float(h));
        }
    }
}
__global__ void mlpack_k(const float* __restrict__ mw, const float* __restrict__ lw,
                         const float* __restrict__ mb, const float* __restrict__ lb,
                         float* __restrict__ W, float* __restrict__ bias)
{
    int idx = blockIdx.x * blockDim.x + threadIdx.x;
    if (idx < H_ * Z_) {
        int k = idx >> 6, j = idx & 63;
        W[k * 128 + j]      = mw[k * Z_ + j];
        W[k * 128 + 64 + j] = lw[k * Z_ + j];
    }
    if (idx < Z_) { bias[idx] = mb[idx]; bias[64 + idx] = lb[idx]; }
}
__global__ void z2_k(const float* __restrict__ ml, const float* __restrict__ eps,
                     float* __restrict__ omu, float* __restrict__ olv, float* __restrict__ z)
{
    int i = blockIdx.x * blockDim.x + threadIdx.x;
    if (i < B_ * Z_) {
        int m = i >> 6, j = i & 63;
        float mu = ml[m * 128 + j], lv = ml[m * 128 + 64 + j];
        omu[i] = mu; olv[i] = lv;
        z[i] = mu + eps[i] * expf(0.5f * lv);
    }
}

// ---------------- launch ----------------
#define SMEM_BIG 197632   // max(1024 + 3*65536, 1024 + 2*98304)

extern "C" void kernel_launch(void* const* d_in, const int* in_sizes, int n_in,
                              void* d_out, int out_size)
{
    const float* x      = (const float*)d_in[0];
    const float* noise  = (const float*)d_in[1];
    const float* epsv   = (const float*)d_in[2];
    const float* wc_w1  = (const float*)d_in[3];
    const float* wc_b1  = (const float*)d_in[4];
    const float* bn_g   = (const float*)d_in[5];
    const float* bn_b   = (const float*)d_in[6];
    const float* wc_w2  = (const float*)d_in[7];
    const float* wc_b2  = (const float*)d_in[8];
    const float* enc_w1 = (const float*)d_in[9];
    const float* enc_b1 = (const float*)d_in[10];
    const float* enc_w2 = (const float*)d_in[11];
    const float* enc_b2 = (const float*)d_in[12];
    const float* enc_w3 = (const float*)d_in[13];
    const float* enc_b3 = (const float*)d_in[14];
    const float* enc_w4 = (const float*)d_in[15];
    const float* enc_b4 = (const float*)d_in[16];
    const float* mean_w = (const float*)d_in[17];
    const float* mean_b = (const float*)d_in[18];
    const float* lv_w   = (const float*)d_in[19];
    const float* lv_b   = (const float*)d_in[20];
    const float* dec_w1 = (const float*)d_in[21];
    const float* dec_b1 = (const float*)d_in[22];
    const float* dec_w2 = (const float*)d_in[23];
    const float* dec_b2 = (const float*)d_in[24];

    float* out      = (float*)d_out;
    float* out_mu_x = out;
    float* out_mu   = out + (size_t)B_ * D_;
    float* out_lv   = out + (size_t)B_ * D_ + (size_t)B_ * Z_;

    float *ph, *pw, *ph1b, *pml, *pz, *pd, *pmlw, *pmlb, *psc, *psh;
    cudaGetSymbolAddress((void**)&ph, g_h);     cudaGetSymbolAddress((void**)&pw, g_w);
    cudaGetSymbolAddress((void**)&ph1b, g_h1b); cudaGetSymbolAddress((void**)&pml, g_ml);
    cudaGetSymbolAddress((void**)&pz, g_z);     cudaGetSymbolAddress((void**)&pd, g_d);
    cudaGetSymbolAddress((void**)&pmlw, g_mlw); cudaGetSymbolAddress((void**)&pmlb, g_mlb);
    cudaGetSymbolAddress((void**)&psc, g_scale);cudaGetSymbolAddress((void**)&psh, g_shift);
    bf16 *pxh, *pxl, *phh, *phl, *pxmh, *pxml, *pa1h, *pa1l, *pa2h, *pa2l, *pa3h, *pa3l,
         *pdh, *pdl, *pw1h, *pw1l, *pw2h, *pw2l, *pe1h, *pe1l, *pe2h, *pe2l, *pe3h, *pe3l,
         *pe4h, *pe4l, *pd2h, *pd2l;
    cudaGetSymbolAddress((void**)&pxh, sx_h);   cudaGetSymbolAddress((void**)&pxl, sx_l);
    cudaGetSymbolAddress((void**)&phh, shh);    cudaGetSymbolAddress((void**)&phl, shl);
    cudaGetSymbolAddress((void**)&pxmh, sxm_h); cudaGetSymbolAddress((void**)&pxml, sxm_l);
    cudaGetSymbolAddress((void**)&pa1h, sa1_h); cudaGetSymbolAddress((void**)&pa1l, sa1_l);
    cudaGetSymbolAddress((void**)&pa2h, sa2_h); cudaGetSymbolAddress((void**)&pa2l, sa2_l);
    cudaGetSymbolAddress((void**)&pa3h, sa3_h); cudaGetSymbolAddress((void**)&pa3l, sa3_l);
    cudaGetSymbolAddress((void**)&pdh, sd_h);   cudaGetSymbolAddress((void**)&pdl, sd_l);
    cudaGetSymbolAddress((void**)&pw1h, w1T_h); cudaGetSymbolAddress((void**)&pw1l, w1T_l);
    cudaGetSymbolAddress((void**)&pw2h, w2T_h); cudaGetSymbolAddress((void**)&pw2l, w2T_l);
    cudaGetSymbolAddress((void**)&pe1h, e1T_h); cudaGetSymbolAddress((void**)&pe1l, e1T_l);
    cudaGetSymbolAddress((void**)&pe2h, e2T_h); cudaGetSymbolAddress((void**)&pe2l, e2T_l);
    cudaGetSymbolAddress((void**)&pe3h, e3T_h); cudaGetSymbolAddress((void**)&pe3l, e3T_l);
    cudaGetSymbolAddress((void**)&pe4h, e4T_h); cudaGetSymbolAddress((void**)&pe4l, e4T_l);
    cudaGetSymbolAddress((void**)&pd2h, d2T_h); cudaGetSymbolAddress((void**)&pd2l, d2T_l);

    cudaFuncSetAttribute(tgemm_k<0, true,  false, 128, 3>, cudaFuncAttributeMaxDynamicSharedMemorySize, SMEM_BIG);
    cudaFuncSetAttribute(tgemm_k<3, true,  false, 256, 2>, cudaFuncAttributeMaxDynamicSharedMemorySize, SMEM_BIG);
    cudaFuncSetAttribute(tgemm_k<1, false, true,  256, 2>, cudaFuncAttributeMaxDynamicSharedMemorySize, SMEM_BIG);
    cudaFuncSetAttribute(tgemm_k<1, false, true,  128, 3>, cudaFuncAttributeMaxDynamicSharedMemorySize, SMEM_BIG);
    cudaFuncSetAttribute(tgemm_k<1, true,  false, 128, 3>, cudaFuncAttributeMaxDynamicSharedMemorySize, SMEM_BIG);
    cudaFuncSetAttribute(tgemm_k<2, true,  false, 256, 2>, cudaFuncAttributeMaxDynamicSharedMemorySize, SMEM_BIG);

    dim3 tb(32, 8);
    // prep: splits & transposes
    xsplit_k<<<B_, 512>>>(x, pxh, pxl);
    wsplitT_k<<<dim3(157, 16),  tb>>>(wc_w1,  D_,  H_,  KP_D, pw1h, pw1l);
    wsplitT_k<<<dim3(16,  157), tb>>>(wc_w2,  H_,  D_,  H_,   pw2h, pw2l);
    wsplitT_k<<<dim3(157, 32),  tb>>>(enc_w1, D_,  H2_, KP_D, pe1h, pe1l);
    wsplitT_k<<<dim3(32,  16),  tb>>>(enc_w2, H2_, H_,  H2_,  pe2h, pe2l);
    wsplitT_k<<<dim3(16,  16),  tb>>>(enc_w3, H_,  H_,  H_,   pe3h, pe3l);
    wsplitT_k<<<dim3(16,  16),  tb>>>(enc_w4, H_,  H_,  H_,   pe4h, pe4l);
    wsplitT_k<<<dim3(32,  157), tb>>>(dec_w2, H2_, D_,  H2_,  pd2h, pd2l);
    mlpack_k<<<(H_ * Z_ + 255) / 256, 256>>>(mean_w, lv_w, mean_b, lv_b, pmlw, pmlb);

    // weight_creator
    tgemm_k<0, true, false, 128, 3><<<dim3(4, 32), 256, SMEM_BIG>>>(
        pxh, pxl, pw1h, pw1l, KP_D, wc_b1, nullptr, ph, nullptr, nullptr, 0, H_, KP_D);
    bnstats_k<<<H_ / 32, tb>>>(ph, bn_g, bn_b, psc, psh);
    hsplit_k<<<B_, H_>>>(ph, psc, psh, phh, phl);
    tgemm_k<3, true, false, 256, 2><<<dim3(20, 32), 256, SMEM_BIG>>>(
        phh, phl, pw2h, pw2l, H_, wc_b2, noise, pw, nullptr, nullptr, 0, D_, H_);

    // top-k + masking (split output)
    topk_k<<<B_, 512>>>(pw, x, pxmh, pxml);

    // encoder
    tgemm_k<1, false, true, 256, 2><<<dim3(4, 32), 256, SMEM_BIG>>>(
        pxmh, pxml, pe1h, pe1l, KP_D, enc_b1, nullptr, nullptr, pa1h, pa1l, H2_, H2_, KP_D);
    tgemm_k<1, false, true, 128, 3><<<dim3(4, 32), 256, SMEM_BIG>>>(
        pa1h, pa1l, pe2h, pe2l, H2_, enc_b2, nullptr, nullptr, pa2h, pa2l, H_, H_, H2_);
    tgemm_k<1, false, true, 128, 3><<<dim3(4, 32), 256, SMEM_BIG>>>(
        pa2h, pa2l, pe3h, pe3l, H_, enc_b3, nullptr, nullptr, pa3h, pa3l, H_, H_, H_);
    tgemm_k<1, true, false, 128, 3><<<dim3(4, 32), 256, SMEM_BIG>>>(
        pa3h, pa3l, pe4h, pe4l, H_, enc_b4, nullptr, ph1b, nullptr, nullptr, 0, H_, H_);

    // mean|logvar (SIMT, N=128 fused), reparameterize
    sgemm_k<0><<<dim3(1, 32), 256>>>(ph1b, pmlw, pmlb, pml, B_, 128, H_);
    z2_k<<<(B_ * Z_ + 255) / 256, 256>>>(pml, epsv, out_mu, out_lv, pz);

    // decoder
    sgemm_k<1><<<dim3(8, 32), 256>>>(pz, dec_w1, dec_b1, pd, B_, H2_, Z_);
    dsplit_k<<<B_, 512>>>(pd, pdh, pdl);
    tgemm_k<2, true, false, 256, 2><<<dim3(20, 32), 256, SMEM_BIG>>>(
        pdh, pdl, pd2h, pd2l, H2_, dec_b2, nullptr, out_mu_x, nullptr, nullptr, 0, D_, H2_);
}

// round 10
// speedup vs baseline: 1.0508x; 1.0508x over previous
#include <cuda_runtime.h>
#include <cuda_bf16.h>
#include <math.h>
#include <stdint.h>

#define B_   4096
#define D_   5000
#define H_   512
#define H2_  1024
#define Z_   64
#define KP_D 5056
#define NP_D 5120

typedef __nv_bfloat16 bf16;

// ---------------- scratch (static device globals; zero-initialized) ---------
__device__ float g_h  [B_ * H_ ];
__device__ float g_w  [B_ * D_ ];
__device__ float g_h1b[B_ * H_ ];
__device__ float g_ml [B_ * 128];
__device__ float g_z  [B_ * Z_ ];
__device__ float g_d  [B_ * H2_];
__device__ float g_mlw[H_ * 128];
__device__ float g_mlb[128];
__device__ float g_scale[H_];
__device__ float g_shift[H_];
__device__ __align__(16) bf16 sx_h [B_ * KP_D], sx_l [B_ * KP_D];
__device__ __align__(16) bf16 shh  [B_ * H_  ], shl  [B_ * H_  ];
__device__ __align__(16) bf16 sxm_h[B_ * KP_D], sxm_l[B_ * KP_D];
__device__ __align__(16) bf16 sa1_h[B_ * H2_ ], sa1_l[B_ * H2_ ];
__device__ __align__(16) bf16 sa2_h[B_ * H_  ], sa2_l[B_ * H_  ];
__device__ __align__(16) bf16 sa3_h[B_ * H_  ], sa3_l[B_ * H_  ];
__device__ __align__(16) bf16 sd_h [B_ * H2_ ], sd_l [B_ * H2_ ];
__device__ __align__(16) bf16 w1T_h[H_   * KP_D], w1T_l[H_   * KP_D];
__device__ __align__(16) bf16 w2T_h[NP_D * H_  ], w2T_l[NP_D * H_  ];
__device__ __align__(16) bf16 e1T_h[H2_  * KP_D], e1T_l[H2_  * KP_D];
__device__ __align__(16) bf16 e2T_h[H_   * H2_ ], e2T_l[H_   * H2_ ];
__device__ __align__(16) bf16 e3T_h[H_   * H_  ], e3T_l[H_   * H_  ];
__device__ __align__(16) bf16 e4T_h[H_   * H_  ], e4T_l[H_   * H_  ];
__device__ __align__(16) bf16 d2T_h[NP_D * H2_ ], d2T_l[NP_D * H2_ ];

// ---------------- PTX helpers (base ISA only) -------------------------------
__device__ __forceinline__ uint32_t smem_u32(const void* p) {
    uint32_t a;
    asm("{ .reg .u64 t; cvta.to.shared.u64 t, %1; cvt.u32.u64 %0, t; }" : "=r"(a) : "l"(p));
    return a;
}
__device__ __forceinline__ void cp16(uint32_t s, const void* g) {
    asm volatile("cp.async.cg.shared.global [%0], [%1], 16;" :: "r"(s), "l"(g));
}
#define CP_COMMIT() asm volatile("cp.async.commit_group;" ::: "memory")
#define CP_WAIT0()  asm volatile("cp.async.wait_group 0;" ::: "memory")
__device__ __forceinline__ void ldsm4(uint32_t* r, uint32_t addr) {
    asm volatile("ldmatrix.sync.aligned.m8n8.x4.shared.b16 {%0,%1,%2,%3}, [%4];"
        : "=r"(r[0]), "=r"(r[1]), "=r"(r[2]), "=r"(r[3]) : "r"(addr));
}
__device__ __forceinline__ void mma16816(float* c, const uint32_t* a, const uint32_t* b) {
    asm volatile("mma.sync.aligned.m16n8k16.row.col.f32.bf16.bf16.f32 "
        "{%0,%1,%2,%3}, {%4,%5,%6,%7}, {%8,%9}, {%0,%1,%2,%3};"
        : "+f"(c[0]), "+f"(c[1]), "+f"(c[2]), "+f"(c[3])
        : "r"(a[0]), "r"(a[1]), "r"(a[2]), "r"(a[3]), "r"(b[0]), "r"(b[1]));
}

// ---------------- HMMA split-bf16 GEMM (128x128, 2-stage) --------------------
// P3=true : 3-pass AhBh + AhBl + AlBh (full split precision)
// P3=false: 2-pass AhBh + AhBl (A-rounding error ~2^-9 kept; used only for
//           the sigmoid-output GEMM whose output is insensitive)
#define STG_SZ  65536
#define SMEM_SZ (2 * STG_SZ + 1024)

template<bool P3>
__device__ __forceinline__ void fill_chunk(uint32_t sb,
    const bf16* Ah, const bf16* Al, const bf16* Bh, const bf16* Bl,
    int ld, int bm, int bn, int k0, int tid)
{
    int rl = tid >> 3, c8 = tid & 7;
#pragma unroll
    for (int i = 0; i < 4; i++) {
        int row = rl + 32 * i;
        uint32_t bo = row * 128 + c8 * 16;
        uint32_t sw = bo ^ ((bo >> 3) & 0x70);
        size_t ga = ((size_t)(bm + row) * ld + k0) * 2 + c8 * 16;
        size_t gb = ((size_t)(bn + row) * ld + k0) * 2 + c8 * 16;
        cp16(sb + sw, (const char*)Ah + ga);
        if (P3) cp16(sb + 16384 + sw, (const char*)Al + ga);
        cp16(sb + 32768 + sw, (const char*)Bh + gb);
        cp16(sb + 49152 + sw, (const char*)Bl + gb);
    }
}

// EPI: 0 bias, 1 leaky, 2 sigmoid, 3 gumbel
template<int EPI, bool OF32, bool OSPL, bool P3>
__global__ void __launch_bounds__(256, 1) tgemm_k(
    const bf16* __restrict__ Ah, const bf16* __restrict__ Al,
    const bf16* __restrict__ Bh, const bf16* __restrict__ Bl, int ldab,
    const float* __restrict__ bias, const float* __restrict__ U,
    float* __restrict__ Cf, bf16* __restrict__ Chi, bf16* __restrict__ Clo,
    int ldspl, int N, int Kpad)
{
    extern __shared__ char dsm[];
    uint32_t sbase = (smem_u32(dsm) + 1023u) & ~1023u;

    const int tid  = threadIdx.x;
    const int wid  = tid >> 5, lane = tid & 31;
    const int wm   = wid & 1,  wn   = wid >> 1;     // warp tile: 64x32
    const int bm   = blockIdx.y * 128;
    const int bn   = blockIdx.x * 128;
    const int NC   = Kpad >> 6;

    float acc[4][4][4];
#pragma unroll
    for (int mi = 0; mi < 4; mi++)
#pragma unroll
        for (int nj = 0; nj < 4; nj++)
#pragma unroll
            for (int q = 0; q < 4; q++) acc[mi][nj][q] = 0.f;

    fill_chunk<P3>(sbase, Ah, Al, Bh, Bl, ldab, bm, bn, 0, tid);
    CP_COMMIT();

    for (int c = 0; c < NC; ++c) {
        CP_WAIT0();
        __syncthreads();
        if (c + 1 < NC) {
            fill_chunk<P3>(sbase + ((c + 1) & 1) * STG_SZ, Ah, Al, Bh, Bl, ldab,
                           bm, bn, (c + 1) << 6, tid);
            CP_COMMIT();
        }
        uint32_t sA  = sbase + (c & 1) * STG_SZ;
        uint32_t sAl = sA + 16384, sB = sA + 32768, sBl = sA + 49152;

#pragma unroll
        for (int ks = 0; ks < 4; ks++) {
            uint32_t ah[4][4], al[4][4], bh[2][4], bl[2][4];
            {
                int arow = wm * 64 + (lane & 15);
                uint32_t akb = ks * 32 + ((lane >> 4) << 4);
#pragma unroll
                for (int mi = 0; mi < 4; mi++) {
                    uint32_t off = (uint32_t)(arow + mi * 16) * 128 + akb;
                    uint32_t sw = off ^ ((off >> 3) & 0x70);
                    ldsm4(ah[mi], sA + sw);
                    if (P3) ldsm4(al[mi], sAl + sw);
                }
            }
            {
                int brow = wn * 32 + ((lane >> 4) << 3) + (lane & 7);
                uint32_t bkb = ks * 32 + (((lane >> 3) & 1) << 4);
#pragma unroll
                for (int jb = 0; jb < 2; jb++) {
                    uint32_t off = (uint32_t)(brow + jb * 16) * 128 + bkb;
                    uint32_t sw = off ^ ((off >> 3) & 0x70);
                    ldsm4(bh[jb], sB + sw);
                    ldsm4(bl[jb], sBl + sw);
                }
            }
#pragma unroll
            for (int mi = 0; mi < 4; mi++)
#pragma unroll
                for (int nj = 0; nj < 4; nj++) {
                    const uint32_t* Bh2 = &bh[nj >> 1][(nj & 1) * 2];
                    const uint32_t* Bl2 = &bl[nj >> 1][(nj & 1) * 2];
                    mma16816(acc[mi][nj], ah[mi], Bh2);
                    mma16816(acc[mi][nj], ah[mi], Bl2);
                    if (P3) mma16816(acc[mi][nj], al[mi], Bh2);
                }
        }
    }

#pragma unroll
    for (int mi = 0; mi < 4; mi++) {
#pragma unroll
        for (int nj = 0; nj < 4; nj++) {
            int row0 = bm + wm * 64 + mi * 16 + (lane >> 2);
            int col0 = bn + wn * 32 + nj * 8 + (lane & 3) * 2;
#pragma unroll
            for (int h = 0; h < 2; h++) {
                int m = row0 + h * 8;
#pragma unroll
                for (int i = 0; i < 2; i++) {
                    int n = col0 + i;
                    if (n < N) {
                        float v = acc[mi][nj][h * 2 + i] + __ldg(&bias[n]);
                        if (EPI == 1) v = (v > 0.f) ? v : 0.01f * v;
                        else if (EPI == 2) v = 1.0f / (1.0f + __expf(-v));
                        else if (EPI == 3) {
                            float u = U[(size_t)m * N + n];
                            u = (1.0f - 1e-30f) * u + 1e-30f;
                            v += __logf(-__logf(u));
                        }
                        if (OF32) Cf[(size_t)m * N + n] = v;
                        if (OSPL) {
                            bf16 hh = __float2bfloat16(v);
                            Chi[(size_t)m * ldspl + n] = hh;
                            Clo[(size_t)m * ldspl + n] = __float2bfloat16(v - __bfloat162float(hh));
                        }
                    }
                }
            }
        }
    }
}

// ---------------- SIMT fp32 GEMM (small layers) ----------------
template<int EPI>
__global__ void __launch_bounds__(256) sgemm_k(
    const float* __restrict__ A, const float* __restrict__ Bm,
    const float* __restrict__ bias, float* __restrict__ C, int M, int N, int K)
{
    constexpr int BM = 128, BNt = 128, BK = 8, TM = 8, TN = 8;
    __shared__ float As[BK][BM];
    __shared__ float Bs[BK][BNt];
    const int tid = threadIdx.x;
    const int tx = tid & 15, ty = tid >> 4;
    const int bm = blockIdx.y * BM, bn = blockIdx.x * BNt;
    const int aIdx = tid * 4, am = aIdx >> 3, ak = aIdx & 7;
    const int bIdx = tid * 4, bk = bIdx >> 7, bn4 = bIdx & 127;
    float acc[TM][TN];
#pragma unroll
    for (int i = 0; i < TM; i++)
#pragma unroll
        for (int j = 0; j < TN; j++) acc[i][j] = 0.f;
    const float* Aptr = A + (size_t)(bm + am) * K;
    for (int k0 = 0; k0 < K; k0 += BK) {
        float4 av = *(const float4*)(Aptr + k0 + ak);
        As[ak + 0][am] = av.x; As[ak + 1][am] = av.y;
        As[ak + 2][am] = av.z; As[ak + 3][am] = av.w;
        const float* Bp = Bm + (size_t)(k0 + bk) * N + bn + bn4;
        int nr = N - (bn + bn4);
        Bs[bk][bn4 + 0] = (0 < nr) ? Bp[0] : 0.f;
        Bs[bk][bn4 + 1] = (1 < nr) ? Bp[1] : 0.f;
        Bs[bk][bn4 + 2] = (2 < nr) ? Bp[2] : 0.f;
        Bs[bk][bn4 + 3] = (3 < nr) ? Bp[3] : 0.f;
        __syncthreads();
#pragma unroll
        for (int kk = 0; kk < BK; kk++) {
            float ar[TM], br[TN];
#pragma unroll
            for (int i = 0; i < TM; i++) ar[i] = As[kk][ty * TM + i];
#pragma unroll
            for (int j = 0; j < TN; j++) br[j] = Bs[kk][tx * TN + j];
#pragma unroll
            for (int i = 0; i < TM; i++)
#pragma unroll
                for (int j = 0; j < TN; j++)
                    acc[i][j] = fmaf(ar[i], br[j], acc[i][j]);
        }
        __syncthreads();
    }
#pragma unroll
    for (int i = 0; i < TM; i++)
#pragma unroll
        for (int j = 0; j < TN; j++) {
            int n = bn + tx * TN + j;
            if (n < N) {
                float v = acc[i][j] + bias[n];
                if (EPI == 1) v = (v > 0.f) ? v : 0.01f * v;
                C[(size_t)(bm + ty * TM + i) * N + n] = v;
            }
        }
}

// ---------------- BN stats (coalesced) ----------------
__global__ void bnstats_k(const float* __restrict__ Hm, const float* __restrict__ gamma,
                          const float* __restrict__ beta, float* __restrict__ sc,
                          float* __restrict__ sh)
{
    int col = blockIdx.x * 32 + threadIdx.x;
    int ty  = threadIdx.y;
    float s = 0.f, q = 0.f;
    for (int r = ty; r < B_; r += 8) {
        float v = Hm[(size_t)r * H_ + col];
        s += v; q += v * v;
    }
    __shared__ float S[8][32], Q[8][32];
    S[ty][threadIdx.x] = s; Q[ty][threadIdx.x] = q;
    __syncthreads();
    if (ty == 0) {
        float SS = 0.f, QQ = 0.f;
#pragma unroll
        for (int i = 0; i < 8; i++) { SS += S[i][threadIdx.x]; QQ += Q[i][threadIdx.x]; }
        float mean = SS / (float)B_;
        float var  = QQ / (float)B_ - mean * mean;
        float scale = gamma[col] * rsqrtf(var + 1e-5f);
        sc[col] = scale; sh[col] = beta[col] - mean * scale;
    }
}

// ---------------- continuous top-k (+ fused split xm) ----------------
__global__ void __launch_bounds__(512) topk_k(const float* __restrict__ W,
                                              const float* __restrict__ X,
                                              bf16* __restrict__ XMh, bf16* __restrict__ XMl)
{
    constexpr int NT = 512, EPT = 10;
    int row = blockIdx.x;
    const float* wr = W + (size_t)row * D_;
    int t = threadIdx.x;
    float wv[EPT], sv[EPT];
#pragma unroll
    for (int i = 0; i < EPT; i++) {
        int idx = t + i * NT;
        wv[i] = (idx < D_) ? wr[idx] : -3.0e38f;
        sv[i] = 0.f;
    }
    __shared__ float red[16];
    __shared__ float bc_max, bc_sum;
    int w = t >> 5, l = t & 31;
    for (int it = 0; it < 50; it++) {
        float m = wv[0];
#pragma unroll
        for (int i = 1; i < EPT; i++) m = fmaxf(m, wv[i]);
#pragma unroll
        for (int o = 16; o > 0; o >>= 1) m = fmaxf(m, __shfl_xor_sync(0xffffffffu, m, o));
        if (l == 0) red[w] = m;
        __syncthreads();
        if (t == 0) {
            float mm = red[0];
            for (int i = 1; i < 16; i++) mm = fmaxf(mm, red[i]);
            bc_max = mm;
        }
        __syncthreads();
        float mx = bc_max, s = 0.f, ev[EPT];
#pragma unroll
        for (int i = 0; i < EPT; i++) {
            float a = (wv[i] - mx) * 10.0f;
            float e = (a > -20.f) ? __expf(a) : 0.f;
            ev[i] = e; s += e;
        }
#pragma unroll
        for (int o = 16; o > 0; o >>= 1) s += __shfl_xor_sync(0xffffffffu, s, o);
        if (l == 0) red[w] = s;
        __syncthreads();
        if (t == 0) {
            float ss = 0.f;
            for (int i = 0; i < 16; i++) ss += red[i];
            bc_sum = ss;
        }
        __syncthreads();
        float inv = 1.0f / bc_sum;
#pragma unroll
        for (int i = 0; i < EPT; i++) {
            float oh = ev[i] * inv;
            sv[i] += oh;
            if (oh > 0.f) wv[i] += __logf(fmaxf(1.0f - oh, 1e-30f));
        }
    }
    const float* xr = X + (size_t)row * D_;
    size_t ob = (size_t)row * KP_D;
#pragma unroll
    for (int i = 0; i < EPT; i++) {
        int idx = t + i * NT;
        if (idx < D_) {
            float v = xr[idx] * sv[i];
            bf16 h = __float2bfloat16(v);
            XMh[ob + idx] = h;
            XMl[ob + idx] = __float2bfloat16(v - __bfloat162float(h));
        }
    }
}

// ---------------- conversion / prep ----------------
__global__ void xsplit_k(const float* __restrict__ x, bf16* __restrict__ hi, bf16* __restrict__ lo)
{
    int m = blockIdx.x;
    for (int c = threadIdx.x; c < D_; c += blockDim.x) {
        float v = x[(size_t)m * D_ + c];
        bf16 h = __float2bfloat16(v);
        size_t o = (size_t)m * KP_D + c;
        hi[o] = h; lo[o] = __float2bfloat16(v - __bfloat162float(h));
    }
}
__global__ void hsplit_k(const float* __restrict__ Hm, const float* __restrict__ sc,
                         const float* __restrict__ sh, bf16* __restrict__ hi, bf16* __restrict__ lo)
{
    int m = blockIdx.x, c = threadIdx.x;
    float v = fmaxf(fmaf(Hm[(size_t)m * H_ + c], sc[c], sh[c]), 0.f);
    bf16 h = __float2bfloat16(v);
    size_t o = (size_t)m * H_ + c;
    hi[o] = h; lo[o] = __float2bfloat16(v - __bfloat162float(h));
}
__global__ void dsplit_k(const float* __restrict__ Dm, bf16* __restrict__ hi, bf16* __restrict__ lo)
{
    int m = blockIdx.x;
    for (int c = threadIdx.x; c < H2_; c += blockDim.x) {
        float v = Dm[(size_t)m * H2_ + c];
        bf16 h = __float2bfloat16(v);
        size_t o = (size_t)m * H2_ + c;
        hi[o] = h; lo[o] = __float2bfloat16(v - __bfloat162float(h));
    }
}

// ---- merged prep: all 7 weight transposes + mean|logvar packing, one launch
__global__ void prep_k(const float* __restrict__ wc_w1, const float* __restrict__ wc_w2,
                       const float* __restrict__ e1w,   const float* __restrict__ e2w,
                       const float* __restrict__ e3w,   const float* __restrict__ e4w,
                       const float* __restrict__ d2w,
                       const float* __restrict__ mw, const float* __restrict__ lw,
                       const float* __restrict__ mb, const float* __restrict__ lb)
{
    int b = blockIdx.x;
    int tx = threadIdx.x, ty = threadIdx.y;

    const float* W; int K, N, Kpad; bf16 *hi, *lo; int local;
    if      (b <  2512) { W = wc_w1; K = D_;  N = H_;  Kpad = KP_D; hi = w1T_h; lo = w1T_l; local = b; }
    else if (b <  5024) { W = wc_w2; K = H_;  N = D_;  Kpad = H_;   hi = w2T_h; lo = w2T_l; local = b - 2512; }
    else if (b < 10048) { W = e1w;   K = D_;  N = H2_; Kpad = KP_D; hi = e1T_h; lo = e1T_l; local = b - 5024; }
    else if (b < 10560) { W = e2w;   K = H2_; N = H_;  Kpad = H2_;  hi = e2T_h; lo = e2T_l; local = b - 10048; }
    else if (b < 10816) { W = e3w;   K = H_;  N = H_;  Kpad = H_;   hi = e3T_h; lo = e3T_l; local = b - 10560; }
    else if (b < 11072) { W = e4w;   K = H_;  N = H_;  Kpad = H_;   hi = e4T_h; lo = e4T_l; local = b - 10816; }
    else if (b < 16096) { W = d2w;   K = H2_; N = D_;  Kpad = H2_;  hi = d2T_h; lo = d2T_l; local = b - 11072; }
    else {  // mean|logvar packing
        int tid = ty * 32 + tx;
        int idx = (b - 16096) * 256 + tid;
        if (idx < H_ * Z_) {
            int k = idx >> 6, j = idx & 63;
            g_mlw[k * 128 + j]      = mw[idx];
            g_mlw[k * 128 + 64 + j] = lw[idx];
        }
        if (idx < Z_) { g_mlb[idx] = mb[idx]; g_mlb[64 + idx] = lb[idx]; }
        return;
    }

    int gx = (K + 31) >> 5;
    int kb = (local % gx) * 32, nb = (local / gx) * 32;

    __shared__ float t[32][33];
#pragma unroll
    for (int j = 0; j < 4; j++) {
        int k = kb + ty + j * 8, n = nb + tx;
        t[ty + j * 8][tx] = (k < K && n < N) ? W[(size_t)k * N + n] : 0.f;
    }
    __syncthreads();
#pragma unroll
    for (int j = 0; j < 4; j++) {
        int n = nb + ty + j * 8, k = kb + tx;
        if (n < N && k < K) {
            float v = t[tx][ty + j * 8];
            bf16 h = __float2bfloat16(v);
            hi[(size_t)n * Kpad + k] = h;
            lo[(size_t)n * Kpad + k] = __float2bfloat16(v - __bfloat162float(h));
        }
    }
}

__global__ void z2_k(const float* __restrict__ ml, const float* __restrict__ eps,
                     float* __restrict__ omu, float* __restrict__ olv, float* __restrict__ z)
{
    int i = blockIdx.x * blockDim.x + threadIdx.x;
    if (i < B_ * Z_) {
        int m = i >> 6, j = i & 63;
        float mu = ml[m * 128 + j], lv = ml[m * 128 + 64 + j];
        omu[i] = mu; olv[i] = lv;
        z[i] = mu + eps[i] * expf(0.5f * lv);
    }
}

// ---------------- launch ----------------
static inline dim3 gT(int N) { return dim3((N + 127) / 128, B_ / 128); }

extern "C" void kernel_launch(void* const* d_in, const int* in_sizes, int n_in,
                              void* d_out, int out_size)
{
    const float* x      = (const float*)d_in[0];
    const float* noise  = (const float*)d_in[1];
    const float* epsv   = (const float*)d_in[2];
    const float* wc_w1  = (const float*)d_in[3];
    const float* wc_b1  = (const float*)d_in[4];
    const float* bn_g   = (const float*)d_in[5];
    const float* bn_b   = (const float*)d_in[6];
    const float* wc_w2  = (const float*)d_in[7];
    const float* wc_b2  = (const float*)d_in[8];
    const float* enc_w1 = (const float*)d_in[9];
    const float* enc_b1 = (const float*)d_in[10];
    const float* enc_w2 = (const float*)d_in[11];
    const float* enc_b2 = (const float*)d_in[12];
    const float* enc_w3 = (const float*)d_in[13];
    const float* enc_b3 = (const float*)d_in[14];
    const float* enc_w4 = (const float*)d_in[15];
    const float* enc_b4 = (const float*)d_in[16];
    const float* mean_w = (const float*)d_in[17];
    const float* mean_b = (const float*)d_in[18];
    const float* lv_w   = (const float*)d_in[19];
    const float* lv_b   = (const float*)d_in[20];
    const float* dec_w1 = (const float*)d_in[21];
    const float* dec_b1 = (const float*)d_in[22];
    const float* dec_w2 = (const float*)d_in[23];
    const float* dec_b2 = (const float*)d_in[24];

    float* out      = (float*)d_out;
    float* out_mu_x = out;
    float* out_mu   = out + (size_t)B_ * D_;
    float* out_lv   = out + (size_t)B_ * D_ + (size_t)B_ * Z_;

    float *ph, *pw, *ph1b, *pml, *pz, *pd, *pmlw, *pmlb, *psc, *psh;
    cudaGetSymbolAddress((void**)&ph, g_h);     cudaGetSymbolAddress((void**)&pw, g_w);
    cudaGetSymbolAddress((void**)&ph1b, g_h1b); cudaGetSymbolAddress((void**)&pml, g_ml);
    cudaGetSymbolAddress((void**)&pz, g_z);     cudaGetSymbolAddress((void**)&pd, g_d);
    cudaGetSymbolAddress((void**)&pmlw, g_mlw); cudaGetSymbolAddress((void**)&pmlb, g_mlb);
    cudaGetSymbolAddress((void**)&psc, g_scale);cudaGetSymbolAddress((void**)&psh, g_shift);
    bf16 *pxh, *pxl, *phh, *phl, *pxmh, *pxml, *pa1h, *pa1l, *pa2h, *pa2l, *pa3h, *pa3l,
         *pdh, *pdl, *pw1h, *pw1l, *pw2h, *pw2l, *pe2h, *pe2l, *pe3h, *pe3l,
         *pe4h, *pe4l, *pd2h, *pd2l, *pe1h, *pe1l;
    cudaGetSymbolAddress((void**)&pxh, sx_h);   cudaGetSymbolAddress((void**)&pxl, sx_l);
    cudaGetSymbolAddress((void**)&phh, shh);    cudaGetSymbolAddress((void**)&phl, shl);
    cudaGetSymbolAddress((void**)&pxmh, sxm_h); cudaGetSymbolAddress((void**)&pxml, sxm_l);
    cudaGetSymbolAddress((void**)&pa1h, sa1_h); cudaGetSymbolAddress((void**)&pa1l, sa1_l);
    cudaGetSymbolAddress((void**)&pa2h, sa2_h); cudaGetSymbolAddress((void**)&pa2l, sa2_l);
    cudaGetSymbolAddress((void**)&pa3h, sa3_h); cudaGetSymbolAddress((void**)&pa3l, sa3_l);
    cudaGetSymbolAddress((void**)&pdh, sd_h);   cudaGetSymbolAddress((void**)&pdl, sd_l);
    cudaGetSymbolAddress((void**)&pw1h, w1T_h); cudaGetSymbolAddress((void**)&pw1l, w1T_l);
    cudaGetSymbolAddress((void**)&pw2h, w2T_h); cudaGetSymbolAddress((void**)&pw2l, w2T_l);
    cudaGetSymbolAddress((void**)&pe1h, e1T_h); cudaGetSymbolAddress((void**)&pe1l, e1T_l);
    cudaGetSymbolAddress((void**)&pe2h, e2T_h); cudaGetSymbolAddress((void**)&pe2l, e2T_l);
    cudaGetSymbolAddress((void**)&pe3h, e3T_h); cudaGetSymbolAddress((void**)&pe3l, e3T_l);
    cudaGetSymbolAddress((void**)&pe4h, e4T_h); cudaGetSymbolAddress((void**)&pe4l, e4T_l);
    cudaGetSymbolAddress((void**)&pd2h, d2T_h); cudaGetSymbolAddress((void**)&pd2l, d2T_l);

    cudaFuncSetAttribute(tgemm_k<0, true,  false, true >, cudaFuncAttributeMaxDynamicSharedMemorySize, SMEM_SZ);
    cudaFuncSetAttribute(tgemm_k<3, true,  false, true >, cudaFuncAttributeMaxDynamicSharedMemorySize, SMEM_SZ);
    cudaFuncSetAttribute(tgemm_k<1, false, true,  true >, cudaFuncAttributeMaxDynamicSharedMemorySize, SMEM_SZ);
    cudaFuncSetAttribute(tgemm_k<1, true,  false, true >, cudaFuncAttributeMaxDynamicSharedMemorySize, SMEM_SZ);
    cudaFuncSetAttribute(tgemm_k<2, true,  false, false>, cudaFuncAttributeMaxDynamicSharedMemorySize, SMEM_SZ);

    dim3 tb(32, 8);
    // 0: x split   1: ALL weight transposes + ml packing (one wave)
    xsplit_k<<<B_, 512>>>(x, pxh, pxl);
    prep_k<<<16224, tb>>>(wc_w1, wc_w2, enc_w1, enc_w2, enc_w3, enc_w4, dec_w2,
                          mean_w, lv_w, mean_b, lv_b);

    // 2: g1   3: bnstats   4: hsplit   5: g2  <- ncu -s 5 profiles g2
    tgemm_k<0, true, false, true><<<gT(H_), 256, SMEM_SZ>>>(
        pxh, pxl, pw1h, pw1l, KP_D, wc_b1, nullptr, ph, nullptr, nullptr, 0, H_, KP_D);
    bnstats_k<<<H_ / 32, tb>>>(ph, bn_g, bn_b, psc, psh);
    hsplit_k<<<B_, H_>>>(ph, psc, psh, phh, phl);
    tgemm_k<3, true, false, true><<<gT(D_), 256, SMEM_SZ>>>(
        phh, phl, pw2h, pw2l, H_, wc_b2, noise, pw, nullptr, nullptr, 0, D_, H_);

    // top-k + masking (split output)
    topk_k<<<B_, 512>>>(pw, x, pxmh, pxml);

    // encoder (all 3-pass: latent chain is precision-sensitive)
    tgemm_k<1, false, true, true><<<gT(H2_), 256, SMEM_SZ>>>(
        pxmh, pxml, pe1h, pe1l, KP_D, enc_b1, nullptr, nullptr, pa1h, pa1l, H2_, H2_, KP_D);
    tgemm_k<1, false, true, true><<<gT(H_), 256, SMEM_SZ>>>(
        pa1h, pa1l, pe2h, pe2l, H2_, enc_b2, nullptr, nullptr, pa2h, pa2l, H_, H_, H2_);
    tgemm_k<1, false, true, true><<<gT(H_), 256, SMEM_SZ>>>(
        pa2h, pa2l, pe3h, pe3l, H_, enc_b3, nullptr, nullptr, pa3h, pa3l, H_, H_, H_);
    tgemm_k<1, true, false, true><<<gT(H_), 256, SMEM_SZ>>>(
        pa3h, pa3l, pe4h, pe4l, H_, enc_b4, nullptr, ph1b, nullptr, nullptr, 0, H_, H_);

    // mean|logvar fused, reparameterize
    sgemm_k<0><<<dim3(1, 32), 256>>>(ph1b, pmlw, pmlb, pml, B_, 128, H_);
    z2_k<<<(B_ * Z_ + 255) / 256, 256>>>(pml, epsv, out_mu, out_lv, pz);

    // decoder (d2: 2-pass — sigmoid output is insensitive to A-rounding)
    sgemm_k<1><<<dim3(8, 32), 256>>>(pz, dec_w1, dec_b1, pd, B_, H2_, Z_);
    dsplit_k<<<B_, 512>>>(pd, pdh, pdl);
    tgemm_k<2, true, false, false><<<gT(D_), 256, SMEM_SZ>>>(
        pdh, pdl, pd2h, pd2l, H2_, dec_b2, nullptr, out_mu_x, nullptr, nullptr, 0, D_, H2_);
}